// round 15
// baseline (speedup 1.0000x reference)
#include <cuda_runtime.h>
#include <cuda_bf16.h>
#include <math.h>

#define B_  64
#define T_  512
#define D_  1024
#define H_  1024
#define G4  4096   // 4*H

#define NCTA   128
#define NTHR   256

// recurrence smem layout (halves)
#define WS_STRIDE 1032
#define AS_STRIDE 136
#define WS_HALVES (32 * WS_STRIDE)
#define AS_HALVES (64 * AS_STRIDE)          // one chunk buffer, one split
// wsH + wsL + 2 bufs asH + 2 bufs asL
#define SMEM_HALVES (2 * WS_HALVES + 4 * AS_HALVES)
#define SMEM_BYTES  (SMEM_HALVES * 2)       // 201728 bytes

// x_proj mma gemm tile
#define XT_STR 40

// ---------------- device-global scratch ----------------
__device__ float g_bp[G4];
__device__ float g_xp[(size_t)B_ * T_ * G4];
__device__ __nv_bfloat16 g_WtHi[(size_t)G4 * H_];
__device__ __nv_bfloat16 g_WtLo[(size_t)G4 * H_];
__device__ __nv_bfloat16 g_WiTHi[(size_t)G4 * D_];
__device__ __nv_bfloat16 g_WiTLo[(size_t)G4 * D_];
__device__ __nv_bfloat16 g_XHi[(size_t)B_ * T_ * D_];
__device__ __nv_bfloat16 g_XLo[(size_t)B_ * T_ * D_];
__device__ __nv_bfloat16 g_hbf[2][2][B_ * H_];
__device__ unsigned g_bar;

typedef unsigned long long ull;
typedef unsigned int u32;

__device__ __forceinline__ float sigmoidf_(float x) { return 1.0f / (1.0f + expf(-x)); }
__device__ __forceinline__ u32 su32(const void* p) {
    return (u32)__cvta_generic_to_shared(p);
}

#define LDSM4(r0, r1, r2, r3, addr) \
    asm volatile("ldmatrix.sync.aligned.m8n8.x4.shared.b16 {%0,%1,%2,%3}, [%4];" \
                 : "=r"(r0), "=r"(r1), "=r"(r2), "=r"(r3) : "r"(addr))

#define MMA_BF16(d, a, b0r, b1r) \
    asm volatile("mma.sync.aligned.m16n8k16.row.col.f32.bf16.bf16.f32 " \
                 "{%0,%1,%2,%3},{%4,%5,%6,%7},{%8,%9},{%0,%1,%2,%3};" \
                 : "+f"(d[0]), "+f"(d[1]), "+f"(d[2]), "+f"(d[3]) \
                 : "r"(a[0]), "r"(a[1]), "r"(a[2]), "r"(a[3]), "r"(b0r), "r"(b1r))

#define CP_ASYNC16(dst, src) \
    asm volatile("cp.async.cg.shared.global [%0], [%1], 16;" :: "r"(dst), "l"(src))
#define CP_COMMIT() asm volatile("cp.async.commit_group;" ::: "memory")
#define CP_WAIT1()  asm volatile("cp.async.wait_group 1;" ::: "memory")
#define CP_WAIT0()  asm volatile("cp.async.wait_group 0;" ::: "memory")

// ---------------- phase 0a (FUSED): X split + bias permute + h init + bar ----
__global__ void fused_prep(const float* __restrict__ X,
                           const float* __restrict__ b,
                           const float* __restrict__ init_h) {
    int idx = blockIdx.x * blockDim.x + threadIdx.x;   // 0 .. 33.5M-1
    float v = X[idx];
    __nv_bfloat16 hi = __float2bfloat16(v);
    g_XHi[idx] = hi;
    g_XLo[idx] = __float2bfloat16(v - __bfloat162float(hi));
    if (idx < B_ * H_) {
        float h = init_h[idx];
        __nv_bfloat16 hh = __float2bfloat16(h);
        g_hbf[0][0][idx] = hh;
        g_hbf[0][1][idx] = __float2bfloat16(h - __bfloat162float(hh));
    }
    if (idx < G4) g_bp[idx] = b[((idx & 3) << 10) + (idx >> 2)];
    if (idx == 0) g_bar = 0u;
}

// ---------------- phase 0b: Wh and Wi -> permuted transposed bf16 split ------
__global__ void wsplit_kernel(const float* __restrict__ Wh,
                              const float* __restrict__ Wi) {
    int idx = blockIdx.x * blockDim.x + threadIdx.x;   // 0 .. 4M-1
    int np = idx >> 10;
    int k  = idx & 1023;
    size_t src = (size_t)k * G4 + ((np & 3) << 10) + (np >> 2);
    float wh = Wh[src];
    __nv_bfloat16 hh = __float2bfloat16(wh);
    g_WtHi[idx] = hh;
    g_WtLo[idx] = __float2bfloat16(wh - __bfloat162float(hh));
    float wi = Wi[src];
    __nv_bfloat16 ih = __float2bfloat16(wi);
    g_WiTHi[idx] = ih;
    g_WiTLo[idx] = __float2bfloat16(wi - __bfloat162float(ih));
}

// ---------------- phase 1: x_proj via tensor cores (unchanged) ------
__global__ __launch_bounds__(256, 2)
void gemm_xproj_mma() {
    __shared__ __nv_bfloat16 xsH[128 * XT_STR];
    __shared__ __nv_bfloat16 xsL[128 * XT_STR];
    __shared__ __nv_bfloat16 wsH[64 * XT_STR];
    __shared__ __nv_bfloat16 wsL[64 * XT_STR];

    const int tid  = threadIdx.x;
    const int wid  = tid >> 5;
    const int lane = tid & 31;
    const int wm   = wid & 3;
    const int wn   = wid >> 2;
    const int m0   = blockIdx.y * 128;
    const int n0   = blockIdx.x * 64;

    const int wrow = tid >> 2;
    const int wc16 = tid & 3;

    const u32 aRowB = (u32)((wm * 32 + (lane & 15)) * XT_STR * 2);
    const u32 aColB = (u32)((lane >> 4) * 16);
    const u32 aH0 = su32(xsH) + aRowB + aColB;
    const u32 aH1 = aH0 + (u32)(16 * XT_STR * 2);
    const u32 aL0 = su32(xsL) + aRowB + aColB;
    const u32 aL1 = aL0 + (u32)(16 * XT_STR * 2);
    const u32 bRow = (u32)(wn * 32 + (lane & 7) + ((lane >> 4) & 1) * 8);
    const u32 bColB = (u32)(((lane >> 3) & 1) * 16);
    const u32 bH0 = su32(wsH) + bRow * (XT_STR * 2) + bColB;
    const u32 bH1 = bH0 + (u32)(16 * XT_STR * 2);
    const u32 bL0 = su32(wsL) + bRow * (XT_STR * 2) + bColB;
    const u32 bL1 = bL0 + (u32)(16 * XT_STR * 2);

    float acc[2][4][4];
    #pragma unroll
    for (int mt = 0; mt < 2; ++mt)
        #pragma unroll
        for (int nt = 0; nt < 4; ++nt)
            #pragma unroll
            for (int j = 0; j < 4; ++j) acc[mt][nt][j] = 0.f;

    uint4 sxH[2], sxL[2], swHr, swLr;
    {
        #pragma unroll
        for (int q = 0; q < 2; ++q) {
            int idx = q * 256 + tid;
            int row = idx >> 2, c16 = idx & 3;
            sxH[q] = *(const uint4*)&g_XHi[(size_t)(m0 + row) * 1024 + c16 * 8];
            sxL[q] = *(const uint4*)&g_XLo[(size_t)(m0 + row) * 1024 + c16 * 8];
        }
        swHr = *(const uint4*)&g_WiTHi[(size_t)(n0 + wrow) * 1024 + wc16 * 8];
        swLr = *(const uint4*)&g_WiTLo[(size_t)(n0 + wrow) * 1024 + wc16 * 8];
    }

    for (int kc = 0; kc < 32; ++kc) {
        #pragma unroll
        for (int q = 0; q < 2; ++q) {
            int idx = q * 256 + tid;
            int row = idx >> 2, c16 = idx & 3;
            *(uint4*)&xsH[row * XT_STR + c16 * 8] = sxH[q];
            *(uint4*)&xsL[row * XT_STR + c16 * 8] = sxL[q];
        }
        *(uint4*)&wsH[wrow * XT_STR + wc16 * 8] = swHr;
        *(uint4*)&wsL[wrow * XT_STR + wc16 * 8] = swLr;
        __syncthreads();

        if (kc < 31) {
            int kb = (kc + 1) * 32;
            #pragma unroll
            for (int q = 0; q < 2; ++q) {
                int idx = q * 256 + tid;
                int row = idx >> 2, c16 = idx & 3;
                sxH[q] = *(const uint4*)&g_XHi[(size_t)(m0 + row) * 1024 + kb + c16 * 8];
                sxL[q] = *(const uint4*)&g_XLo[(size_t)(m0 + row) * 1024 + kb + c16 * 8];
            }
            swHr = *(const uint4*)&g_WiTHi[(size_t)(n0 + wrow) * 1024 + kb + wc16 * 8];
            swLr = *(const uint4*)&g_WiTLo[(size_t)(n0 + wrow) * 1024 + kb + wc16 * 8];
        }

        #pragma unroll
        for (int ks = 0; ks < 2; ++ks) {
            const u32 kb = (u32)(ks * 32);
            u32 aH[2][4], aL[2][4], bH[2][4], bL[2][4];
            LDSM4(aH[0][0], aH[0][1], aH[0][2], aH[0][3], aH0 + kb);
            LDSM4(aH[1][0], aH[1][1], aH[1][2], aH[1][3], aH1 + kb);
            LDSM4(aL[0][0], aL[0][1], aL[0][2], aL[0][3], aL0 + kb);
            LDSM4(aL[1][0], aL[1][1], aL[1][2], aL[1][3], aL1 + kb);
            LDSM4(bH[0][0], bH[0][1], bH[0][2], bH[0][3], bH0 + kb);
            LDSM4(bH[1][0], bH[1][1], bH[1][2], bH[1][3], bH1 + kb);
            LDSM4(bL[0][0], bL[0][1], bL[0][2], bL[0][3], bL0 + kb);
            LDSM4(bL[1][0], bL[1][1], bL[1][2], bL[1][3], bL1 + kb);

            #pragma unroll
            for (int mt = 0; mt < 2; ++mt) {
                #pragma unroll
                for (int ng = 0; ng < 2; ++ng) {
                    MMA_BF16(acc[mt][2 * ng + 0], aH[mt], bH[ng][0], bH[ng][1]);
                    MMA_BF16(acc[mt][2 * ng + 1], aH[mt], bH[ng][2], bH[ng][3]);
                    MMA_BF16(acc[mt][2 * ng + 0], aH[mt], bL[ng][0], bL[ng][1]);
                    MMA_BF16(acc[mt][2 * ng + 1], aH[mt], bL[ng][2], bL[ng][3]);
                    MMA_BF16(acc[mt][2 * ng + 0], aL[mt], bH[ng][0], bH[ng][1]);
                    MMA_BF16(acc[mt][2 * ng + 1], aL[mt], bH[ng][2], bH[ng][3]);
                }
            }
        }
        __syncthreads();
    }

    #pragma unroll
    for (int mt = 0; mt < 2; ++mt) {
        int r = m0 + wm * 32 + mt * 16 + (lane >> 2);
        #pragma unroll
        for (int nt = 0; nt < 4; ++nt) {
            int cc = n0 + wn * 32 + nt * 8 + 2 * (lane & 3);
            float2 b2 = *(const float2*)&g_bp[cc];
            float2 r0 = make_float2(acc[mt][nt][0] + b2.x, acc[mt][nt][1] + b2.y);
            float2 r1 = make_float2(acc[mt][nt][2] + b2.x, acc[mt][nt][3] + b2.y);
            *(float2*)&g_xp[(size_t)r * G4 + cc] = r0;
            *(float2*)&g_xp[(size_t)(r + 8) * G4 + cc] = r1;
        }
    }
}

// ---------------- phase 2: persistent LSTM recurrence ----------------
// 256 threads / 8 warps. NEW vs R14:
//  - split arrive/wait barrier: publish h -> arrive, THEN write out[]/finals
//    and prefetch xp(t+1) while other CTAs arrive (stores off critical path)
//  - cp.async (depth-2 commit groups) for h staging, no register staging
__global__ __launch_bounds__(NTHR, 1)
void lstm_mma(const float* __restrict__ init_c,
              const int*   __restrict__ lengths,
              float* __restrict__ out) {
    extern __shared__ __nv_bfloat16 sm[];
    __nv_bfloat16* wsH = sm;
    __nv_bfloat16* wsL = sm + WS_HALVES;
    __nv_bfloat16* asH = sm + 2 * WS_HALVES;                   // 2 buffers
    __nv_bfloat16* asL = sm + 2 * WS_HALVES + 2 * AS_HALVES;   // 2 buffers

    const int tid  = threadIdx.x;
    const int wid  = tid >> 5;
    const int lane = tid & 31;
    const int mg   = wid >> 1;
    const int nh   = wid & 1;
    const int n0   = blockIdx.x * 32;

    #pragma unroll 4
    for (int i = 0; i < 16; ++i) {
        int idx = i * NTHR + tid;
        int row = idx >> 7;
        int c16 = idx & 127;
        *(uint4*)&wsH[row * WS_STRIDE + c16 * 8] =
            *(const uint4*)&g_WtHi[(size_t)(n0 + row) * 1024 + c16 * 8];
        *(uint4*)&wsL[row * WS_STRIDE + c16 * 8] =
            *(const uint4*)&g_WtLo[(size_t)(n0 + row) * 1024 + c16 * 8];
    }
    __syncthreads();

    const int b   = mg * 16 + (lane >> 2) + (lane & 1) * 8;
    const int hcb = (n0 >> 2) + nh * 4 + ((lane & 3) >> 1);
    float creg[2];
    #pragma unroll
    for (int nt = 0; nt < 2; ++nt) creg[nt] = init_c[b * H_ + hcb + 2 * nt];
    const int len = lengths[b];

    const u32 aFrag = (u32)(((mg * 16 + (lane & 15)) * AS_STRIDE + (lane >> 4) * 8) * 2);
    const u32 aH0 = su32(asH) + aFrag;
    const u32 aL0 = su32(asL) + aFrag;
    const u32 ABUF = (u32)(AS_HALVES * 2);
    const u32 bRow0 = (u32)(nh * 16 + (lane & 7) + ((lane >> 4) & 1) * 8);
    const u32 bColB = (u32)(((lane >> 3) & 1) * 16);
    const u32 bOffH = su32(wsH) + bRow0 * (WS_STRIDE * 2) + bColB;
    const u32 bOffL = su32(wsL) + bRow0 * (WS_STRIDE * 2) + bColB;

    // cp.async staging bases for this thread (4 x 16B per split per chunk)
    const u32 dstH = su32(asH);
    const u32 dstL = su32(asL);

    const size_t fc_off = (size_t)B_ * T_ * H_;
    const size_t fh_off = fc_off + (size_t)B_ * H_;
    volatile unsigned* vbar = &g_bar;

    // xp prefetch for t=0
    float4 xpv[2];
    #pragma unroll
    for (int nt = 0; nt < 2; ++nt)
        xpv[nt] = __ldg((const float4*)&g_xp[((size_t)b * T_) * G4 + (hcb + 2 * nt) * 4]);

    for (int t = 0; t < T_; ++t) {
        // ---- WAIT: h(t) published by all CTAs ----
        if (tid == 0 && t > 0) {
            while (*vbar < (unsigned)NCTA * (unsigned)t) { }
            __threadfence();
        }
        __syncthreads();

        const __nv_bfloat16* hH = g_hbf[t & 1][0];
        const __nv_bfloat16* hL = g_hbf[t & 1][1];

        // ---- issue chunks 0,1 via cp.async ----
        #pragma unroll
        for (int pc = 0; pc < 2; ++pc) {
            const int kb = pc * 128;
            const u32 bo = (u32)pc * ABUF;
            #pragma unroll
            for (int q = 0; q < 4; ++q) {
                int idx = q * NTHR + tid;
                int row = idx >> 4;
                int c16 = idx & 15;
                u32 off = (u32)((row * AS_STRIDE + c16 * 8) * 2);
                CP_ASYNC16(dstH + bo + off, (const void*)&hH[(size_t)row * H_ + kb + c16 * 8]);
                CP_ASYNC16(dstL + bo + off, (const void*)&hL[(size_t)row * H_ + kb + c16 * 8]);
            }
            CP_COMMIT();
        }

        float dm[2][4], dc[2][4];
        #pragma unroll
        for (int nt = 0; nt < 2; ++nt)
            #pragma unroll
            for (int j = 0; j < 4; ++j) { dm[nt][j] = 0.f; dc[nt][j] = 0.f; }

        for (int ch = 0; ch < 8; ++ch) {
            if (ch < 7) { CP_WAIT1(); } else { CP_WAIT0(); }
            __syncthreads();

            const u32 pOff = (u32)(ch & 1) * ABUF;
            #pragma unroll
            for (int ks = 0; ks < 8; ++ks) {
                const u32 kByte = (u32)((ch * 128 + ks * 16) * 2);
                u32 ah[4], al[4], bh[4], bl[4];
                LDSM4(ah[0], ah[1], ah[2], ah[3], aH0 + pOff + (u32)(ks * 32));
                LDSM4(al[0], al[1], al[2], al[3], aL0 + pOff + (u32)(ks * 32));
                LDSM4(bh[0], bh[1], bh[2], bh[3], bOffH + kByte);
                LDSM4(bl[0], bl[1], bl[2], bl[3], bOffL + kByte);

                MMA_BF16(dm[0], ah, bh[0], bh[1]);
                MMA_BF16(dm[1], ah, bh[2], bh[3]);
                MMA_BF16(dc[0], ah, bl[0], bl[1]);
                MMA_BF16(dc[1], ah, bl[2], bl[3]);
                MMA_BF16(dc[0], al, bh[0], bh[1]);
                MMA_BF16(dc[1], al, bh[2], bh[3]);
            }
            __syncthreads();

            if (ch < 6) {
                const int kb = (ch + 2) * 128;
                const u32 bo = (u32)(ch & 1) * ABUF;
                #pragma unroll
                for (int q = 0; q < 4; ++q) {
                    int idx = q * NTHR + tid;
                    int row = idx >> 4;
                    int c16 = idx & 15;
                    u32 off = (u32)((row * AS_STRIDE + c16 * 8) * 2);
                    CP_ASYNC16(dstH + bo + off, (const void*)&hH[(size_t)row * H_ + kb + c16 * 8]);
                    CP_ASYNC16(dstL + bo + off, (const void*)&hL[(size_t)row * H_ + kb + c16 * 8]);
                }
                CP_COMMIT();
            }
        }

        // ---- epilogue part 1: gates + PUBLISH h ----
        __nv_bfloat16* nxtH = g_hbf[(t + 1) & 1][0];
        __nv_bfloat16* nxtL = g_hbf[(t + 1) & 1][1];
        const bool odd = (lane & 1);
        float hval[2], cval[2];
        #pragma unroll
        for (int nt = 0; nt < 2; ++nt) {
            float d0 = dm[nt][0] + dc[nt][0];
            float d1 = dm[nt][1] + dc[nt][1];
            float d2 = dm[nt][2] + dc[nt][2];
            float d3 = dm[nt][3] + dc[nt][3];
            float s0 = __shfl_xor_sync(0xffffffffu, d0, 1);
            float s1 = __shfl_xor_sync(0xffffffffu, d1, 1);
            float s2 = __shfl_xor_sync(0xffffffffu, d2, 1);
            float s3 = __shfl_xor_sync(0xffffffffu, d3, 1);
            float zi = odd ? s2 : d0;
            float zf = odd ? s3 : d1;
            float zg = odd ? d2 : s0;
            float zo = odd ? d3 : s1;
            zi += xpv[nt].x; zf += xpv[nt].y; zg += xpv[nt].z; zo += xpv[nt].w;
            float ig = sigmoidf_(zi);
            float fg = sigmoidf_(zf);
            float gg = tanhf(zg);
            float og = sigmoidf_(zo);
            float c = fg * creg[nt] + ig * gg;
            float h = og * tanhf(c);
            creg[nt] = c;
            cval[nt] = c;
            hval[nt] = h;
            int hc = hcb + 2 * nt;
            __nv_bfloat16 hhi = __float2bfloat16(h);
            nxtH[b * H_ + hc] = hhi;
            nxtL[b * H_ + hc] = __float2bfloat16(h - __bfloat162float(hhi));
        }
        __threadfence();
        __syncthreads();

        // ---- ARRIVE (no spin) ----
        if (tid == 0) atomicAdd(&g_bar, 1u);

        // ---- epilogue part 2 (off critical path): out writes + xp prefetch --
        #pragma unroll
        for (int nt = 0; nt < 2; ++nt) {
            int hc = hcb + 2 * nt;
            out[((size_t)b * T_ + t) * H_ + hc] = hval[nt];
            if (t == len - 1) {
                out[fc_off + b * H_ + hc] = cval[nt];
                out[fh_off + b * H_ + hc] = hval[nt];
            }
        }
        if (t + 1 < T_) {
            #pragma unroll
            for (int nt = 0; nt < 2; ++nt)
                xpv[nt] = __ldg((const float4*)&g_xp[((size_t)b * T_ + (t + 1)) * G4 + (hcb + 2 * nt) * 4]);
        }
    }
}

// ---------------- launch ----------------
extern "C" void kernel_launch(void* const* d_in, const int* in_sizes, int n_in,
                              void* d_out, int out_size) {
    const float* inputs  = (const float*)d_in[0];
    const int*   lengths = (const int*)  d_in[1];
    const float* init_c  = (const float*)d_in[2];
    const float* init_h  = (const float*)d_in[3];
    const float* Wi      = (const float*)d_in[4];
    const float* Wh      = (const float*)d_in[5];
    const float* b       = (const float*)d_in[6];
    float* out = (float*)d_out;

    cudaFuncSetAttribute(lstm_mma,
                         cudaFuncAttributeMaxDynamicSharedMemorySize, SMEM_BYTES);

    fused_prep<<<(B_ * T_ * D_) / 256, 256>>>(inputs, b, init_h);
    wsplit_kernel<<<(G4 * H_) / 256, 256>>>(Wh, Wi);
    gemm_xproj_mma<<<dim3(G4 / 64, (B_ * T_) / 128), 256>>>();
    lstm_mma<<<NCTA, NTHR, SMEM_BYTES>>>(init_c, lengths, out);
}

// round 17
// speedup vs baseline: 1.2676x; 1.2676x over previous
#include <cuda_runtime.h>
#include <cuda_bf16.h>
#include <cuda_fp16.h>
#include <math.h>

#define B_  64
#define T_  512
#define D_  1024
#define H_  1024
#define G4  4096   // 4*H

#define NCTA   128
#define NTHR   256

// recurrence smem layout (halves)
#define WS_STRIDE 1032
#define AS_STRIDE 136
#define WS_HALVES (32 * WS_STRIDE)
#define AS_HALVES (64 * AS_STRIDE)
// wsHi + wsLo + 1 staged h buffer
#define SMEM_HALVES (2 * WS_HALVES + AS_HALVES)
#define SMEM_BYTES  (SMEM_HALVES * 2)       // 149504 bytes

// x_proj mma gemm tile
#define XT_STR 40

// ---------------- device-global scratch ----------------
__device__ float g_bp[G4];
__device__ float g_xp[(size_t)B_ * T_ * G4];
__device__ __half g_WtHi[(size_t)G4 * H_];        // Wh^T permuted [np][k], fp16 hi
__device__ __half g_WtLo[(size_t)G4 * H_];        // fp16 lo (residual)
__device__ __nv_bfloat16 g_WiTHi[(size_t)G4 * D_]; // Wi^T permuted (bf16 split, gemm)
__device__ __nv_bfloat16 g_WiTLo[(size_t)G4 * D_];
__device__ __nv_bfloat16 g_XHi[(size_t)B_ * T_ * D_];
__device__ __nv_bfloat16 g_XLo[(size_t)B_ * T_ * D_];
__device__ __half g_hf[2][B_ * H_];               // hidden state fp16, double buffered
__device__ unsigned g_bar;

typedef unsigned long long ull;
typedef unsigned int u32;

__device__ __forceinline__ float sigmoidf_(float x) { return 1.0f / (1.0f + expf(-x)); }
__device__ __forceinline__ u32 su32(const void* p) {
    return (u32)__cvta_generic_to_shared(p);
}

#define LDSM4(r0, r1, r2, r3, addr) \
    asm volatile("ldmatrix.sync.aligned.m8n8.x4.shared.b16 {%0,%1,%2,%3}, [%4];" \
                 : "=r"(r0), "=r"(r1), "=r"(r2), "=r"(r3) : "r"(addr))

#define MMA_BF16(d, a, b0r, b1r) \
    asm volatile("mma.sync.aligned.m16n8k16.row.col.f32.bf16.bf16.f32 " \
                 "{%0,%1,%2,%3},{%4,%5,%6,%7},{%8,%9},{%0,%1,%2,%3};" \
                 : "+f"(d[0]), "+f"(d[1]), "+f"(d[2]), "+f"(d[3]) \
                 : "r"(a[0]), "r"(a[1]), "r"(a[2]), "r"(a[3]), "r"(b0r), "r"(b1r))

#define MMA_F16(d, a, b0r, b1r) \
    asm volatile("mma.sync.aligned.m16n8k16.row.col.f32.f16.f16.f32 " \
                 "{%0,%1,%2,%3},{%4,%5,%6,%7},{%8,%9},{%0,%1,%2,%3};" \
                 : "+f"(d[0]), "+f"(d[1]), "+f"(d[2]), "+f"(d[3]) \
                 : "r"(a[0]), "r"(a[1]), "r"(a[2]), "r"(a[3]), "r"(b0r), "r"(b1r))

// ---------------- phase 0a (FUSED): X split + bias permute + h init + bar ----
__global__ void fused_prep(const float* __restrict__ X,
                           const float* __restrict__ b,
                           const float* __restrict__ init_h) {
    int idx = blockIdx.x * blockDim.x + threadIdx.x;
    float v = X[idx];
    __nv_bfloat16 hi = __float2bfloat16(v);
    g_XHi[idx] = hi;
    g_XLo[idx] = __float2bfloat16(v - __bfloat162float(hi));
    if (idx < B_ * H_) g_hf[0][idx] = __float2half(init_h[idx]);
    if (idx < G4) g_bp[idx] = b[((idx & 3) << 10) + (idx >> 2)];
    if (idx == 0) g_bar = 0u;
}

// ---------------- phase 0b: Wh (fp16 split) + Wi (bf16 split) ------
__global__ void wsplit_kernel(const float* __restrict__ Wh,
                              const float* __restrict__ Wi) {
    int idx = blockIdx.x * blockDim.x + threadIdx.x;   // 0 .. 4M-1
    int np = idx >> 10;
    int k  = idx & 1023;
    size_t src = (size_t)k * G4 + ((np & 3) << 10) + (np >> 2);
    float wh = Wh[src];
    __half whh = __float2half(wh);
    g_WtHi[idx] = whh;
    g_WtLo[idx] = __float2half(wh - __half2float(whh));
    float wi = Wi[src];
    __nv_bfloat16 ih = __float2bfloat16(wi);
    g_WiTHi[idx] = ih;
    g_WiTLo[idx] = __float2bfloat16(wi - __bfloat162float(ih));
}

// ---------------- phase 1: x_proj via tensor cores (unchanged) ------
__global__ __launch_bounds__(256, 2)
void gemm_xproj_mma() {
    __shared__ __nv_bfloat16 xsH[128 * XT_STR];
    __shared__ __nv_bfloat16 xsL[128 * XT_STR];
    __shared__ __nv_bfloat16 wsH[64 * XT_STR];
    __shared__ __nv_bfloat16 wsL[64 * XT_STR];

    const int tid  = threadIdx.x;
    const int wid  = tid >> 5;
    const int lane = tid & 31;
    const int wm   = wid & 3;
    const int wn   = wid >> 2;
    const int m0   = blockIdx.y * 128;
    const int n0   = blockIdx.x * 64;

    const int wrow = tid >> 2;
    const int wc16 = tid & 3;

    const u32 aRowB = (u32)((wm * 32 + (lane & 15)) * XT_STR * 2);
    const u32 aColB = (u32)((lane >> 4) * 16);
    const u32 aH0 = su32(xsH) + aRowB + aColB;
    const u32 aH1 = aH0 + (u32)(16 * XT_STR * 2);
    const u32 aL0 = su32(xsL) + aRowB + aColB;
    const u32 aL1 = aL0 + (u32)(16 * XT_STR * 2);
    const u32 bRow = (u32)(wn * 32 + (lane & 7) + ((lane >> 4) & 1) * 8);
    const u32 bColB = (u32)(((lane >> 3) & 1) * 16);
    const u32 bH0 = su32(wsH) + bRow * (XT_STR * 2) + bColB;
    const u32 bH1 = bH0 + (u32)(16 * XT_STR * 2);
    const u32 bL0 = su32(wsL) + bRow * (XT_STR * 2) + bColB;
    const u32 bL1 = bL0 + (u32)(16 * XT_STR * 2);

    float acc[2][4][4];
    #pragma unroll
    for (int mt = 0; mt < 2; ++mt)
        #pragma unroll
        for (int nt = 0; nt < 4; ++nt)
            #pragma unroll
            for (int j = 0; j < 4; ++j) acc[mt][nt][j] = 0.f;

    uint4 sxH[2], sxL[2], swHr, swLr;
    {
        #pragma unroll
        for (int q = 0; q < 2; ++q) {
            int idx = q * 256 + tid;
            int row = idx >> 2, c16 = idx & 3;
            sxH[q] = *(const uint4*)&g_XHi[(size_t)(m0 + row) * 1024 + c16 * 8];
            sxL[q] = *(const uint4*)&g_XLo[(size_t)(m0 + row) * 1024 + c16 * 8];
        }
        swHr = *(const uint4*)&g_WiTHi[(size_t)(n0 + wrow) * 1024 + wc16 * 8];
        swLr = *(const uint4*)&g_WiTLo[(size_t)(n0 + wrow) * 1024 + wc16 * 8];
    }

    for (int kc = 0; kc < 32; ++kc) {
        #pragma unroll
        for (int q = 0; q < 2; ++q) {
            int idx = q * 256 + tid;
            int row = idx >> 2, c16 = idx & 3;
            *(uint4*)&xsH[row * XT_STR + c16 * 8] = sxH[q];
            *(uint4*)&xsL[row * XT_STR + c16 * 8] = sxL[q];
        }
        *(uint4*)&wsH[wrow * XT_STR + wc16 * 8] = swHr;
        *(uint4*)&wsL[wrow * XT_STR + wc16 * 8] = swLr;
        __syncthreads();

        if (kc < 31) {
            int kb = (kc + 1) * 32;
            #pragma unroll
            for (int q = 0; q < 2; ++q) {
                int idx = q * 256 + tid;
                int row = idx >> 2, c16 = idx & 3;
                sxH[q] = *(const uint4*)&g_XHi[(size_t)(m0 + row) * 1024 + kb + c16 * 8];
                sxL[q] = *(const uint4*)&g_XLo[(size_t)(m0 + row) * 1024 + kb + c16 * 8];
            }
            swHr = *(const uint4*)&g_WiTHi[(size_t)(n0 + wrow) * 1024 + kb + wc16 * 8];
            swLr = *(const uint4*)&g_WiTLo[(size_t)(n0 + wrow) * 1024 + kb + wc16 * 8];
        }

        #pragma unroll
        for (int ks = 0; ks < 2; ++ks) {
            const u32 kb = (u32)(ks * 32);
            u32 aH[2][4], aL[2][4], bH[2][4], bL[2][4];
            LDSM4(aH[0][0], aH[0][1], aH[0][2], aH[0][3], aH0 + kb);
            LDSM4(aH[1][0], aH[1][1], aH[1][2], aH[1][3], aH1 + kb);
            LDSM4(aL[0][0], aL[0][1], aL[0][2], aL[0][3], aL0 + kb);
            LDSM4(aL[1][0], aL[1][1], aL[1][2], aL[1][3], aL1 + kb);
            LDSM4(bH[0][0], bH[0][1], bH[0][2], bH[0][3], bH0 + kb);
            LDSM4(bH[1][0], bH[1][1], bH[1][2], bH[1][3], bH1 + kb);
            LDSM4(bL[0][0], bL[0][1], bL[0][2], bL[0][3], bL0 + kb);
            LDSM4(bL[1][0], bL[1][1], bL[1][2], bL[1][3], bL1 + kb);

            #pragma unroll
            for (int mt = 0; mt < 2; ++mt) {
                #pragma unroll
                for (int ng = 0; ng < 2; ++ng) {
                    MMA_BF16(acc[mt][2 * ng + 0], aH[mt], bH[ng][0], bH[ng][1]);
                    MMA_BF16(acc[mt][2 * ng + 1], aH[mt], bH[ng][2], bH[ng][3]);
                    MMA_BF16(acc[mt][2 * ng + 0], aH[mt], bL[ng][0], bL[ng][1]);
                    MMA_BF16(acc[mt][2 * ng + 1], aH[mt], bL[ng][2], bL[ng][3]);
                    MMA_BF16(acc[mt][2 * ng + 0], aL[mt], bH[ng][0], bH[ng][1]);
                    MMA_BF16(acc[mt][2 * ng + 1], aL[mt], bH[ng][2], bH[ng][3]);
                }
            }
        }
        __syncthreads();
    }

    #pragma unroll
    for (int mt = 0; mt < 2; ++mt) {
        int r = m0 + wm * 32 + mt * 16 + (lane >> 2);
        #pragma unroll
        for (int nt = 0; nt < 4; ++nt) {
            int cc = n0 + wn * 32 + nt * 8 + 2 * (lane & 3);
            float2 b2 = *(const float2*)&g_bp[cc];
            float2 r0 = make_float2(acc[mt][nt][0] + b2.x, acc[mt][nt][1] + b2.y);
            float2 r1 = make_float2(acc[mt][nt][2] + b2.x, acc[mt][nt][3] + b2.y);
            *(float2*)&g_xp[(size_t)r * G4 + cc] = r0;
            *(float2*)&g_xp[(size_t)(r + 8) * G4 + cc] = r1;
        }
    }
}

// ---------------- phase 2: persistent LSTM recurrence ----------------
// h single fp16, Wh 2-term fp16 split. Staging: full chunk = 1024 uint4
// = 4 uint4/thread (R16 bug: was 2 -> half the chunk uninitialized -> NaN).
__global__ __launch_bounds__(NTHR, 1)
void lstm_mma(const float* __restrict__ init_c,
              const int*   __restrict__ lengths,
              float* __restrict__ out) {
    extern __shared__ __half sm[];
    __half* wsHi = sm;                       // [32][1032] fp16
    __half* wsLo = sm + WS_HALVES;
    __half* as   = sm + 2 * WS_HALVES;       // [64][136] staged h fp16

    const int tid  = threadIdx.x;
    const int wid  = tid >> 5;
    const int lane = tid & 31;
    const int mg   = wid >> 1;       // m group: batches 16mg..16mg+15
    const int nh   = wid & 1;        // n half: cols n0+16nh..+16
    const int n0   = blockIdx.x * 32;

    // ---- load W^T slice (once) ----
    #pragma unroll 4
    for (int i = 0; i < 16; ++i) {
        int idx = i * NTHR + tid;
        int row = idx >> 7;
        int c16 = idx & 127;
        *(uint4*)&wsHi[row * WS_STRIDE + c16 * 8] =
            *(const uint4*)&g_WtHi[(size_t)(n0 + row) * 1024 + c16 * 8];
        *(uint4*)&wsLo[row * WS_STRIDE + c16 * 8] =
            *(const uint4*)&g_WtLo[(size_t)(n0 + row) * 1024 + c16 * 8];
    }
    __syncthreads();

    const int b   = mg * 16 + (lane >> 2) + (lane & 1) * 8;
    const int hcb = (n0 >> 2) + nh * 4 + ((lane & 3) >> 1);
    float creg[2];
    #pragma unroll
    for (int nt = 0; nt < 2; ++nt) creg[nt] = init_c[b * H_ + hcb + 2 * nt];
    const int len = lengths[b];

    const u32 aFrag = (u32)(((mg * 16 + (lane & 15)) * AS_STRIDE + (lane >> 4) * 8) * 2);
    const u32 aOff = su32(as) + aFrag;
    const u32 bRow0 = (u32)(nh * 16 + (lane & 7) + ((lane >> 4) & 1) * 8);
    const u32 bColB = (u32)(((lane >> 3) & 1) * 16);
    const u32 bOffH = su32(wsHi) + bRow0 * (WS_STRIDE * 2) + bColB;
    const u32 bOffL = su32(wsLo) + bRow0 * (WS_STRIDE * 2) + bColB;

    const size_t fc_off = (size_t)B_ * T_ * H_;
    const size_t fh_off = fc_off + (size_t)B_ * H_;
    volatile unsigned* vbar = &g_bar;

    for (int t = 0; t < T_; ++t) {
        // xp prefetch (independent of h)
        float4 xpv[2];
        #pragma unroll
        for (int nt = 0; nt < 2; ++nt)
            xpv[nt] = __ldg((const float4*)&g_xp[((size_t)b * T_ + t) * G4 + (hcb + 2 * nt) * 4]);

        // ---- grid barrier ----
        __syncthreads();
        if (tid == 0) {
            __threadfence();
            atomicAdd(&g_bar, 1u);
            unsigned target = (unsigned)NCTA * (unsigned)(t + 1);
            while (*vbar < target) { }
            __threadfence();
        }
        __syncthreads();

        const __half* hS = g_hf[t & 1];

        float dm[2][4], dc[2][4];
        #pragma unroll
        for (int nt = 0; nt < 2; ++nt)
            #pragma unroll
            for (int j = 0; j < 4; ++j) { dm[nt][j] = 0.f; dc[nt][j] = 0.f; }

        // ---- prefetch chunk 0: full chunk = 1024 uint4 = 4 per thread ----
        uint4 pre[4];
        #pragma unroll
        for (int q = 0; q < 4; ++q) {
            int idx = q * NTHR + tid;
            int row = idx >> 4;
            int c16 = idx & 15;
            pre[q] = *(const uint4*)&hS[row * H_ + c16 * 8];
        }

        for (int ch = 0; ch < 8; ++ch) {
            #pragma unroll
            for (int q = 0; q < 4; ++q) {
                int idx = q * NTHR + tid;
                int row = idx >> 4;
                int c16 = idx & 15;
                *(uint4*)&as[row * AS_STRIDE + c16 * 8] = pre[q];
            }
            __syncthreads();

            if (ch < 7) {
                #pragma unroll
                for (int q = 0; q < 4; ++q) {
                    int idx = q * NTHR + tid;
                    int row = idx >> 4;
                    int c16 = idx & 15;
                    pre[q] = *(const uint4*)&hS[row * H_ + (ch + 1) * 128 + c16 * 8];
                }
            }

            #pragma unroll
            for (int ks = 0; ks < 8; ++ks) {
                const u32 kByte = (u32)((ch * 128 + ks * 16) * 2);
                u32 ah[4], bh[4], bl[4];
                LDSM4(ah[0], ah[1], ah[2], ah[3], aOff + (u32)(ks * 32));
                LDSM4(bh[0], bh[1], bh[2], bh[3], bOffH + kByte);
                LDSM4(bl[0], bl[1], bl[2], bl[3], bOffL + kByte);

                MMA_F16(dm[0], ah, bh[0], bh[1]);
                MMA_F16(dm[1], ah, bh[2], bh[3]);
                MMA_F16(dc[0], ah, bl[0], bl[1]);
                MMA_F16(dc[1], ah, bl[2], bl[3]);
            }
            __syncthreads();
        }

        // ---- epilogue: gates + state update for 2 (b, hc) cells ----
        __half* nxt = g_hf[(t + 1) & 1];
        const bool odd = (lane & 1);
        #pragma unroll
        for (int nt = 0; nt < 2; ++nt) {
            float d0 = dm[nt][0] + dc[nt][0];
            float d1 = dm[nt][1] + dc[nt][1];
            float d2 = dm[nt][2] + dc[nt][2];
            float d3 = dm[nt][3] + dc[nt][3];
            float s0 = __shfl_xor_sync(0xffffffffu, d0, 1);
            float s1 = __shfl_xor_sync(0xffffffffu, d1, 1);
            float s2 = __shfl_xor_sync(0xffffffffu, d2, 1);
            float s3 = __shfl_xor_sync(0xffffffffu, d3, 1);
            float zi = odd ? s2 : d0;
            float zf = odd ? s3 : d1;
            float zg = odd ? d2 : s0;
            float zo = odd ? d3 : s1;
            zi += xpv[nt].x; zf += xpv[nt].y; zg += xpv[nt].z; zo += xpv[nt].w;
            float ig = sigmoidf_(zi);
            float fg = sigmoidf_(zf);
            float gg = tanhf(zg);
            float og = sigmoidf_(zo);
            float c = fg * creg[nt] + ig * gg;
            float h = og * tanhf(c);
            creg[nt] = c;
            int hc = hcb + 2 * nt;
            out[((size_t)b * T_ + t) * H_ + hc] = h;
            if (t == len - 1) {
                out[fc_off + b * H_ + hc] = c;
                out[fh_off + b * H_ + hc] = h;
            }
            nxt[b * H_ + hc] = __float2half(h);
        }
    }
}

// ---------------- launch ----------------
extern "C" void kernel_launch(void* const* d_in, const int* in_sizes, int n_in,
                              void* d_out, int out_size) {
    const float* inputs  = (const float*)d_in[0];
    const int*   lengths = (const int*)  d_in[1];
    const float* init_c  = (const float*)d_in[2];
    const float* init_h  = (const float*)d_in[3];
    const float* Wi      = (const float*)d_in[4];
    const float* Wh      = (const float*)d_in[5];
    const float* b       = (const float*)d_in[6];
    float* out = (float*)d_out;

    cudaFuncSetAttribute(lstm_mma,
                         cudaFuncAttributeMaxDynamicSharedMemorySize, SMEM_BYTES);

    fused_prep<<<(B_ * T_ * D_) / 256, 256>>>(inputs, b, init_h);
    wsplit_kernel<<<(G4 * H_) / 256, 256>>>(Wh, Wi);
    gemm_xproj_mma<<<dim3(G4 / 64, (B_ * T_) / 128), 256>>>();
    lstm_mma<<<NCTA, NTHR, SMEM_BYTES>>>(init_c, lengths, out);
}